// round 7
// baseline (speedup 1.0000x reference)
#include <cuda_runtime.h>
#include <cuda_bf16.h>
#include <cstdint>

// ---------------------------------------------------------------------------
// Problem constants
// ---------------------------------------------------------------------------
#define NP      63                 // patches per dim
#define NPATCH  3969               // 63*63
#define BL      15876              // 4 * 3969
#define MPAD    16000              // 125 * 128
#define IND     4096
#define HIDD    256

// ---------------------------------------------------------------------------
// Scratch
// ---------------------------------------------------------------------------
__device__ __nv_bfloat16 g_Xb[(size_t)4 * 64 * 256 * 256];  // x in bf16
__device__ __nv_bfloat16 g_H[(size_t)MPAD * HIDD];
__device__ __nv_bfloat16 g_Y[(size_t)MPAD * IND];
__device__ __nv_bfloat16 g_W1[(size_t)HIDD * IND];
__device__ __nv_bfloat16 g_W2[(size_t)IND * HIDD];

// ---------------------------------------------------------------------------
// PTX helpers
// ---------------------------------------------------------------------------
__device__ __forceinline__ void cp_async16(uint32_t s, const void* g) {
    asm volatile("cp.async.cg.shared.global [%0], [%1], 16;\n" ::"r"(s), "l"(g));
}
// 8-byte cp.async with zero-fill: copies sz bytes (0 or 8), zero-pads to 8.
__device__ __forceinline__ void cp_async8z(uint32_t s, const void* g, uint32_t sz) {
    asm volatile("cp.async.ca.shared.global [%0], [%1], 8, %2;\n"
                 ::"r"(s), "l"(g), "r"(sz));
}
__device__ __forceinline__ void cp_commit() {
    asm volatile("cp.async.commit_group;\n");
}
template <int N>
__device__ __forceinline__ void cp_wait() {
    asm volatile("cp.async.wait_group %0;\n" ::"n"(N));
}
__device__ __forceinline__ void ldmx4(uint32_t& r0, uint32_t& r1, uint32_t& r2,
                                      uint32_t& r3, uint32_t addr) {
    asm volatile("ldmatrix.sync.aligned.m8n8.x4.shared.b16 {%0,%1,%2,%3}, [%4];\n"
                 : "=r"(r0), "=r"(r1), "=r"(r2), "=r"(r3)
                 : "r"(addr));
}
__device__ __forceinline__ void mma16816(float c[4], const uint32_t a[4],
                                         const uint32_t b[2]) {
    asm volatile(
        "mma.sync.aligned.m16n8k16.row.col.f32.bf16.bf16.f32 "
        "{%0,%1,%2,%3}, {%4,%5,%6,%7}, {%8,%9}, {%0,%1,%2,%3};\n"
        : "+f"(c[0]), "+f"(c[1]), "+f"(c[2]), "+f"(c[3])
        : "r"(a[0]), "r"(a[1]), "r"(a[2]), "r"(a[3]), "r"(b[0]), "r"(b[1]));
}

// Swizzled byte offset for an Rx32 bf16 tile stored as R/2 phys rows of 128B.
// Conflict-free for cp.async stores and ldmatrix reads (verified R2/R4/R5).
__device__ __forceinline__ uint32_t sw_off(int r, int kc) {
    int pr = r >> 1;
    int pc = (((r & 1) << 2) | kc) ^ (pr & 7);
    return (uint32_t)((pr << 7) + (pc << 4));
}

__device__ __forceinline__ float gelu_exact(float v) {
    return 0.5f * v * (1.0f + erff(v * 0.70710678118654752f));
}

// ---------------------------------------------------------------------------
// Kernel 1a: convert weights to bf16 (both exactly 1048576 elems)
// ---------------------------------------------------------------------------
__global__ void convert_weights(const float* __restrict__ W1,
                                const float* __restrict__ W2) {
    int i = (blockIdx.x * 256 + threadIdx.x) * 4;
    float4 a = *(const float4*)(W1 + i);
    float4 b = *(const float4*)(W2 + i);
    union { uint2 u; __nv_bfloat162 h[2]; } pa, pb;
    pa.h[0] = __floats2bfloat162_rn(a.x, a.y);
    pa.h[1] = __floats2bfloat162_rn(a.z, a.w);
    pb.h[0] = __floats2bfloat162_rn(b.x, b.y);
    pb.h[1] = __floats2bfloat162_rn(b.z, b.w);
    *(uint2*)(g_W1 + i) = pa.u;
    *(uint2*)(g_W2 + i) = pb.u;
}

// ---------------------------------------------------------------------------
// Kernel 1b: convert x to bf16 (16,777,216 elems)
// ---------------------------------------------------------------------------
__global__ void convert_x(const float* __restrict__ x) {
    int i = (blockIdx.x * 256 + threadIdx.x) * 4;
    float4 f = *(const float4*)(x + i);
    union { uint2 u; __nv_bfloat162 h[2]; } v;
    v.h[0] = __floats2bfloat162_rn(f.x, f.y);
    v.h[1] = __floats2bfloat162_rn(f.z, f.w);
    *(uint2*)(g_Xb + i) = v.u;
}

// ---------------------------------------------------------------------------
// Kernel 2: GEMM1 fused with patchify.  H = GELU(P @ W1^T + b1)
// 128x128x32 tiles, 256 threads, 2 CTAs/SM, 5-stage pipeline.
// grid (2, 125): x = N tile, y = M tile (A-tile L2 reuse across wave).
// ---------------------------------------------------------------------------
__global__ void __launch_bounds__(256, 2)
gemm1_fused(const float* __restrict__ bias, __nv_bfloat16* __restrict__ H) {
    constexpr int STAGES = 5;
    constexpr int ABYTES = 8192;   // 128 x 32 bf16
    constexpr int BBYTES = 8192;   // 128 x 32 bf16
    constexpr int STAGE_BYTES = ABYTES + BBYTES;  // 16 KB, 5 stages = 80 KB
    extern __shared__ __align__(128) uint8_t smem_raw[];
    const uint32_t smem = (uint32_t)__cvta_generic_to_shared(smem_raw);

    const int tid = threadIdx.x;
    const int lane = tid & 31, warp = tid >> 5;
    const int wm = warp >> 1, wn = warp & 1;
    const int bm = blockIdx.y * 128;
    const long bn = (long)blockIdx.x * 128;
    constexpr int K = 4096, N = 256, KT = 128;

    // per-thread A gather geometry: 2 chunks per thread
    const __nv_bfloat16* aptr[2];
    uint32_t asz[2], asw[2];
#pragma unroll
    for (int i = 0; i < 2; i++) {
        int q = tid + (i << 8);
        int r = q >> 2, kc = q & 3;
        int m = bm + r;
        bool valid = (m < BL);
        int b = m / NPATCH;
        int l = m - b * NPATCH;
        int ih = l / NP;
        int iw = l - ih * NP;
        aptr[i] = valid ? g_Xb + ((size_t)b << 22) + (ih * 4 + kc) * 256 + iw * 4
                        : g_Xb;
        asz[i] = valid ? 8u : 0u;
        asw[i] = sw_off(r, kc);
    }

    float acc[2][8][4];
#pragma unroll
    for (int i = 0; i < 2; i++)
#pragma unroll
        for (int j = 0; j < 8; j++)
#pragma unroll
            for (int k = 0; k < 4; k++) acc[i][j][k] = 0.0f;

    auto load_stage = [&](int kt) {
        uint32_t sA = smem + (kt % STAGES) * STAGE_BYTES;
        uint32_t sB = sA + ABYTES;
        // A: gather. chunk kt -> c = kt>>1, kh0 = (kt&1)*4 (elements offset)
        long aoff = ((kt >> 1) << 16) + ((kt & 1) << 10);
#pragma unroll
        for (int i = 0; i < 2; i++) {
            const __nv_bfloat16* as = aptr[i] + aoff;
            cp_async8z(sA + asw[i], as, asz[i]);
            cp_async8z(sA + asw[i] + 8, as + 4, asz[i]);
        }
        // B: W1 rows bn..bn+128 (K-major, stride 4096)
        const __nv_bfloat16* Bg = g_W1 + bn * K + kt * 32;
#pragma unroll
        for (int i = 0; i < 2; i++) {
            int q = tid + (i << 8);
            int r = q >> 2, kc = q & 3;
            cp_async16(sB + sw_off(r, kc), Bg + (long)r * K + (kc << 3));
        }
    };

    load_stage(0); cp_commit();
    load_stage(1); cp_commit();
    load_stage(2); cp_commit();
    load_stage(3); cp_commit();

    for (int kt = 0; kt < KT; kt++) {
        if (kt + 2 < KT) cp_wait<3>(); else cp_wait<0>();
        __syncthreads();
        int kn = kt + 4;
        if (kn < KT) load_stage(kn);
        cp_commit();

        uint32_t sA = smem + (kt % STAGES) * STAGE_BYTES;
        uint32_t sB = sA + ABYTES;
#pragma unroll
        for (int kk = 0; kk < 2; kk++) {
            uint32_t a[2][4];
#pragma unroll
            for (int mi = 0; mi < 2; mi++) {
                int r = wm * 32 + mi * 16 + (lane & 15);
                int kc = (kk << 1) | (lane >> 4);
                ldmx4(a[mi][0], a[mi][1], a[mi][2], a[mi][3], sA + sw_off(r, kc));
            }
            uint32_t bfr[8][2];
#pragma unroll
            for (int nj = 0; nj < 4; nj++) {
                int r = wn * 64 + nj * 16 + (lane & 7) + ((lane & 16) >> 1);
                int kc = (kk << 1) | ((lane >> 3) & 1);
                uint32_t t0, t1, t2, t3;
                ldmx4(t0, t1, t2, t3, sB + sw_off(r, kc));
                bfr[nj * 2][0] = t0; bfr[nj * 2][1] = t1;
                bfr[nj * 2 + 1][0] = t2; bfr[nj * 2 + 1][1] = t3;
            }
#pragma unroll
            for (int mi = 0; mi < 2; mi++)
#pragma unroll
                for (int ni = 0; ni < 8; ni++) mma16816(acc[mi][ni], a[mi], bfr[ni]);
        }
    }

    const long crow = bm + wm * 32 + (lane >> 2);
#pragma unroll
    for (int mi = 0; mi < 2; mi++) {
#pragma unroll
        for (int ni = 0; ni < 8; ni++) {
            long col = bn + wn * 64 + ni * 8 + ((lane & 3) << 1);
            float b0 = bias[col], b1 = bias[col + 1];
            float v0 = gelu_exact(acc[mi][ni][0] + b0);
            float v1 = gelu_exact(acc[mi][ni][1] + b1);
            float v2 = gelu_exact(acc[mi][ni][2] + b0);
            float v3 = gelu_exact(acc[mi][ni][3] + b1);
            long r0 = crow + mi * 16;
            *(__nv_bfloat162*)(H + r0 * N + col) = __floats2bfloat162_rn(v0, v1);
            *(__nv_bfloat162*)(H + (r0 + 8) * N + col) = __floats2bfloat162_rn(v2, v3);
        }
    }
}

// ---------------------------------------------------------------------------
// Kernel 3: GEMM2  Y = H @ W2^T + b2.  128x128x32 tiles, 256 threads,
// 2 CTAs/SM, 4 stages. grid (32, 125): x = N tile (B L2-hot), y = M tile.
// ---------------------------------------------------------------------------
__global__ void __launch_bounds__(256, 2)
gemm2(const __nv_bfloat16* __restrict__ A, const __nv_bfloat16* __restrict__ Bw,
      const float* __restrict__ bias, __nv_bfloat16* __restrict__ C) {
    constexpr int ABYTES = 8192;
    constexpr int BBYTES = 8192;
    constexpr int STAGE_BYTES = ABYTES + BBYTES;  // 16 KB, 4 stages = 64 KB
    constexpr int K = 256, N = 4096, KT = 8;
    extern __shared__ __align__(128) uint8_t smem_raw[];
    const uint32_t smem = (uint32_t)__cvta_generic_to_shared(smem_raw);

    const int tid = threadIdx.x;
    const int lane = tid & 31, warp = tid >> 5;
    const int wm = warp >> 1, wn = warp & 1;
    const long bm = (long)blockIdx.y * 128;
    const long bn = (long)blockIdx.x * 128;

    float acc[2][8][4];
#pragma unroll
    for (int i = 0; i < 2; i++)
#pragma unroll
        for (int j = 0; j < 8; j++)
#pragma unroll
            for (int k = 0; k < 4; k++) acc[i][j][k] = 0.0f;

    auto load_stage = [&](int kt) {
        const __nv_bfloat16* Ag = A + bm * K + kt * 32;
        const __nv_bfloat16* Bg = Bw + bn * K + kt * 32;
        uint32_t sA = smem + (kt & 3) * STAGE_BYTES;
        uint32_t sB = sA + ABYTES;
#pragma unroll
        for (int i = 0; i < 2; i++) {
            int q = tid + (i << 8);
            int r = q >> 2, kc = q & 3;
            cp_async16(sA + sw_off(r, kc), Ag + (long)r * K + (kc << 3));
        }
#pragma unroll
        for (int i = 0; i < 2; i++) {
            int q = tid + (i << 8);
            int r = q >> 2, kc = q & 3;
            cp_async16(sB + sw_off(r, kc), Bg + (long)r * K + (kc << 3));
        }
    };

    load_stage(0); cp_commit();
    load_stage(1); cp_commit();
    load_stage(2); cp_commit();

    for (int kt = 0; kt < KT; kt++) {
        if (kt + 2 < KT) cp_wait<2>(); else cp_wait<0>();
        __syncthreads();
        int kn = kt + 3;
        if (kn < KT) load_stage(kn);
        cp_commit();

        uint32_t sA = smem + (kt & 3) * STAGE_BYTES;
        uint32_t sB = sA + ABYTES;
#pragma unroll
        for (int kk = 0; kk < 2; kk++) {
            uint32_t a[2][4];
#pragma unroll
            for (int mi = 0; mi < 2; mi++) {
                int r = wm * 32 + mi * 16 + (lane & 15);
                int kc = (kk << 1) | (lane >> 4);
                ldmx4(a[mi][0], a[mi][1], a[mi][2], a[mi][3], sA + sw_off(r, kc));
            }
            uint32_t bfr[8][2];
#pragma unroll
            for (int nj = 0; nj < 4; nj++) {
                int r = wn * 64 + nj * 16 + (lane & 7) + ((lane & 16) >> 1);
                int kc = (kk << 1) | ((lane >> 3) & 1);
                uint32_t t0, t1, t2, t3;
                ldmx4(t0, t1, t2, t3, sB + sw_off(r, kc));
                bfr[nj * 2][0] = t0; bfr[nj * 2][1] = t1;
                bfr[nj * 2 + 1][0] = t2; bfr[nj * 2 + 1][1] = t3;
            }
#pragma unroll
            for (int mi = 0; mi < 2; mi++)
#pragma unroll
                for (int ni = 0; ni < 8; ni++) mma16816(acc[mi][ni], a[mi], bfr[ni]);
        }
    }

    const long crow = bm + wm * 32 + (lane >> 2);
#pragma unroll
    for (int mi = 0; mi < 2; mi++) {
#pragma unroll
        for (int ni = 0; ni < 8; ni++) {
            long col = bn + wn * 64 + ni * 8 + ((lane & 3) << 1);
            float b0 = bias[col], b1 = bias[col + 1];
            float v0 = acc[mi][ni][0] + b0;
            float v1 = acc[mi][ni][1] + b1;
            float v2 = acc[mi][ni][2] + b0;
            float v3 = acc[mi][ni][3] + b1;
            long r0 = crow + mi * 16;
            *(__nv_bfloat162*)(C + r0 * N + col) = __floats2bfloat162_rn(v0, v1);
            *(__nv_bfloat162*)(C + (r0 + 8) * N + col) = __floats2bfloat162_rn(v2, v3);
        }
    }
}

// ---------------------------------------------------------------------------
// Kernel 4: gather-fold + residual
// out = x + softplus(alpha_raw) * fold(Y)/norm
// ---------------------------------------------------------------------------
__global__ void fold_kernel(const float* __restrict__ x,
                            const float* __restrict__ alpha_raw,
                            float* __restrict__ out) {
    int t = blockIdx.x * 256 + threadIdx.x;  // 4,194,304 threads
    int w0 = (t & 63) << 2;
    int h = (t >> 6) & 255;
    int c = (t >> 14) & 63;
    int b = t >> 20;

    float alpha = log1pf(__expf(alpha_raw[0]));

    int ih_lo = max(0, (h - 4) >> 2);
    int ih_hi = min(62, h >> 2);
    int iw_lo = max(0, (w0 - 4) >> 2);
    int iw_hi = min(62, w0 >> 2);
    int cnt = (ih_hi - ih_lo + 1) * (iw_hi - iw_lo + 1);

    float s0 = 0.f, s1 = 0.f, s2 = 0.f, s3 = 0.f;
    for (int ih = ih_lo; ih <= ih_hi; ih++) {
        int kh = h - 4 * ih;
        for (int iw = iw_lo; iw <= iw_hi; iw++) {
            int kw0 = w0 - 4 * iw;
            size_t m = (size_t)b * NPATCH + ih * NP + iw;
            const __nv_bfloat162* p =
                (const __nv_bfloat162*)(g_Y + m * IND + c * 64 + kh * 8 + kw0);
            __nv_bfloat162 v01 = p[0];
            __nv_bfloat162 v23 = p[1];
            s0 += __low2float(v01); s1 += __high2float(v01);
            s2 += __low2float(v23); s3 += __high2float(v23);
        }
    }
    float sc = alpha / (float)cnt;
    size_t xi = (size_t)t * 4;
    float4 xv = *(const float4*)(x + xi);
    float4 o;
    o.x = fmaf(s0, sc, xv.x);
    o.y = fmaf(s1, sc, xv.y);
    o.z = fmaf(s2, sc, xv.z);
    o.w = fmaf(s3, sc, xv.w);
    *(float4*)(out + xi) = o;
}

// ---------------------------------------------------------------------------
// Launch
// ---------------------------------------------------------------------------
extern "C" void kernel_launch(void* const* d_in, const int* in_sizes, int n_in,
                              void* d_out, int out_size) {
    const float* x         = (const float*)d_in[0];
    const float* W1        = (const float*)d_in[1];
    const float* b1        = (const float*)d_in[2];
    const float* W2        = (const float*)d_in[3];
    const float* b2        = (const float*)d_in[4];
    const float* alpha_raw = (const float*)d_in[5];
    float* out             = (float*)d_out;

    void *pH, *pY, *pW2;
    cudaGetSymbolAddress(&pH, g_H);
    cudaGetSymbolAddress(&pY, g_Y);
    cudaGetSymbolAddress(&pW2, g_W2);

    const int SM1 = 5 * 16384;  // 80 KB
    const int SM2 = 4 * 16384;  // 64 KB
    cudaFuncSetAttribute(gemm1_fused,
                         cudaFuncAttributeMaxDynamicSharedMemorySize, SM1);
    cudaFuncSetAttribute(gemm2,
                         cudaFuncAttributeMaxDynamicSharedMemorySize, SM2);

    convert_weights<<<1024, 256>>>(W1, W2);
    convert_x<<<16384, 256>>>(x);
    // GEMM1 (+patchify): H = GELU(P @ W1^T + b1)  M=16000, N=256, K=4096
    gemm1_fused<<<dim3(2, 125), 256, SM1>>>(b1, (__nv_bfloat16*)pH);
    // GEMM2: Y = H @ W2^T + b2                    M=16000, N=4096, K=256
    gemm2<<<dim3(32, 125), 256, SM2>>>(
        (const __nv_bfloat16*)pH, (const __nv_bfloat16*)pW2, b2,
        (__nv_bfloat16*)pY);
    fold_kernel<<<16384, 256>>>(x, alpha_raw, out);
}

// round 8
// speedup vs baseline: 1.0235x; 1.0235x over previous
#include <cuda_runtime.h>
#include <cuda_bf16.h>
#include <cstdint>

// ---------------------------------------------------------------------------
// Problem constants
// ---------------------------------------------------------------------------
#define NP      63                 // patches per dim
#define NPATCH  3969               // 63*63
#define BL      15876              // 4 * 3969
#define MPAD    16000              // 125 * 128
#define IND     4096
#define HIDD    256

// fp8 scaling (dodges e4m3 subnormal floor):
//   Xf8 = 4*x, W1f8 = 16*W1  -> acc1/64 = P@W1
//   Hf8 = 4*H, W2f8 = 1024*W2 -> acc2/4096 = H@W2
#define SX     4.0f
#define SW1    16.0f
#define INV_S1 (1.0f / 64.0f)
#define SH     4.0f
#define SW2    1024.0f
#define INV_S2 (1.0f / 4096.0f)

// ---------------------------------------------------------------------------
// Scratch
// ---------------------------------------------------------------------------
__device__ uint8_t g_Xf8[(size_t)4 * 64 * 256 * 256];   // 16 MB, scaled x
__device__ uint8_t g_Hf8[(size_t)MPAD * HIDD];          // 4 MB, scaled H
__device__ uint8_t g_W1f8[(size_t)HIDD * IND];          // 1 MB
__device__ uint8_t g_W2f8[(size_t)IND * HIDD];          // 1 MB
__device__ __nv_bfloat16 g_Y[(size_t)MPAD * IND];       // 128 MB

// ---------------------------------------------------------------------------
// PTX helpers
// ---------------------------------------------------------------------------
__device__ __forceinline__ void cp_async16(uint32_t s, const void* g) {
    asm volatile("cp.async.cg.shared.global [%0], [%1], 16;\n" ::"r"(s), "l"(g));
}
__device__ __forceinline__ void cp_async8z(uint32_t s, const void* g, uint32_t sz) {
    asm volatile("cp.async.ca.shared.global [%0], [%1], 8, %2;\n"
                 ::"r"(s), "l"(g), "r"(sz));
}
__device__ __forceinline__ void cp_commit() {
    asm volatile("cp.async.commit_group;\n");
}
template <int N>
__device__ __forceinline__ void cp_wait() {
    asm volatile("cp.async.wait_group %0;\n" ::"n"(N));
}
__device__ __forceinline__ void ldmx4(uint32_t& r0, uint32_t& r1, uint32_t& r2,
                                      uint32_t& r3, uint32_t addr) {
    asm volatile("ldmatrix.sync.aligned.m8n8.x4.shared.b16 {%0,%1,%2,%3}, [%4];\n"
                 : "=r"(r0), "=r"(r1), "=r"(r2), "=r"(r3)
                 : "r"(addr));
}
// fp8 e4m3 MMA, K=32, f32 accumulate (sm_89+)
__device__ __forceinline__ void mma16832(float c[4], const uint32_t a[4],
                                         const uint32_t b[2]) {
    asm volatile(
        "mma.sync.aligned.m16n8k32.row.col.f32.e4m3.e4m3.f32 "
        "{%0,%1,%2,%3}, {%4,%5,%6,%7}, {%8,%9}, {%0,%1,%2,%3};\n"
        : "+f"(c[0]), "+f"(c[1]), "+f"(c[2]), "+f"(c[3])
        : "r"(a[0]), "r"(a[1]), "r"(a[2]), "r"(a[3]), "r"(b[0]), "r"(b[1]));
}
// pack two floats -> e4m3x2 (lo = v0, hi = v1)
__device__ __forceinline__ uint16_t pack2_e4m3(float v0, float v1) {
    uint16_t u;
    asm("cvt.rn.satfinite.e4m3x2.f32 %0, %1, %2;" : "=h"(u) : "f"(v1), "f"(v0));
    return u;
}
__device__ __forceinline__ uint32_t pack4_e4m3(float v0, float v1, float v2,
                                               float v3) {
    uint32_t lo = pack2_e4m3(v0, v1), hi = pack2_e4m3(v2, v3);
    return lo | (hi << 16);
}

// Swizzled byte offset for an Rx64B tile stored as R/2 phys rows of 128B.
// (r, kc): r = tile row, kc = 16B chunk (0..3). Same geometry as the verified
// bf16 Rx32 tiles (identical byte layout), conflict-free for cp.async stores
// and ldmatrix reads.
__device__ __forceinline__ uint32_t sw_off(int r, int kc) {
    int pr = r >> 1;
    int pc = (((r & 1) << 2) | kc) ^ (pr & 7);
    return (uint32_t)((pr << 7) + (pc << 4));
}

__device__ __forceinline__ float gelu_exact(float v) {
    return 0.5f * v * (1.0f + erff(v * 0.70710678118654752f));
}

// ---------------------------------------------------------------------------
// Kernel 1a: weights -> scaled fp8 (both exactly 1048576 elems)
// ---------------------------------------------------------------------------
__global__ void convert_weights(const float* __restrict__ W1,
                                const float* __restrict__ W2) {
    int i = (blockIdx.x * 256 + threadIdx.x) * 4;
    float4 a = *(const float4*)(W1 + i);
    float4 b = *(const float4*)(W2 + i);
    *(uint32_t*)(g_W1f8 + i) =
        pack4_e4m3(a.x * SW1, a.y * SW1, a.z * SW1, a.w * SW1);
    *(uint32_t*)(g_W2f8 + i) =
        pack4_e4m3(b.x * SW2, b.y * SW2, b.z * SW2, b.w * SW2);
}

// ---------------------------------------------------------------------------
// Kernel 1b: x -> scaled fp8 (16,777,216 elems)
// ---------------------------------------------------------------------------
__global__ void convert_x(const float* __restrict__ x) {
    int i = (blockIdx.x * 256 + threadIdx.x) * 4;
    float4 f = *(const float4*)(x + i);
    *(uint32_t*)(g_Xf8 + i) =
        pack4_e4m3(f.x * SX, f.y * SX, f.z * SX, f.w * SX);
}

// ---------------------------------------------------------------------------
// Kernel 2: GEMM1 fused with patchify (fp8).  H = GELU(P @ W1^T + b1)
// CTA tile 128x256, K-chunk = 64 fp8 bytes (= channel c's 8x8 block),
// 512 threads (16 warps 4x4, warp tile 32x64), 4-stage cp.async, KT=64.
// ---------------------------------------------------------------------------
__global__ void __launch_bounds__(512, 1)
gemm1_fused(const float* __restrict__ bias) {
    constexpr int ABYTES = 8192;    // 128 rows x 64 B
    constexpr int BBYTES = 16384;   // 256 rows x 64 B
    constexpr int STAGE_BYTES = ABYTES + BBYTES;  // 24 KB x 4 = 96 KB
    constexpr int KBY = 4096, KT = 64;
    extern __shared__ __align__(128) uint8_t smem_raw[];
    const uint32_t smem = (uint32_t)__cvta_generic_to_shared(smem_raw);

    const int tid = threadIdx.x;
    const int lane = tid & 31, warp = tid >> 5;
    const int wm = warp >> 2, wn = warp & 3;
    const int bm = blockIdx.x * 128;

    // per-thread A gather: chunk (r = tid>>2, kc = tid&3) = pixel rows
    // kh = 2kc, 2kc+1 (8 pixels each) of channel c = kt.
    const int ar = tid >> 2, akc = tid & 3;
    const int m = bm + ar;
    const bool valid = (m < BL);
    int b = m / NPATCH;
    int l = m - b * NPATCH;
    int ih = l / NP;
    int iw = l - ih * NP;
    const uint8_t* aptr =
        valid ? g_Xf8 + ((size_t)b << 22) + (ih * 4 + 2 * akc) * 256 + iw * 4
              : g_Xf8;
    const uint32_t asz = valid ? 8u : 0u;
    const uint32_t asw = sw_off(ar, akc);

    float acc[2][8][4];
#pragma unroll
    for (int i = 0; i < 2; i++)
#pragma unroll
        for (int j = 0; j < 8; j++)
#pragma unroll
            for (int k = 0; k < 4; k++) acc[i][j][k] = 0.0f;

    auto load_stage = [&](int kt) {
        uint32_t sA = smem + (kt & 3) * STAGE_BYTES;
        uint32_t sB = sA + ABYTES;
        // A gather: channel kt -> +kt*65536 bytes; rows 2kc, 2kc+1
        const uint8_t* as = aptr + ((size_t)kt << 16);
        cp_async8z(sA + asw, as, asz);
        cp_async8z(sA + asw + 8, as + 256, asz);
        // B: W1f8 rows (4096 B stride), 64 B chunk at kt*64
        const uint8_t* Bg = g_W1f8 + kt * 64;
#pragma unroll
        for (int i = 0; i < 2; i++) {
            int q = tid + (i << 9);
            int r = q >> 2, kc = q & 3;
            cp_async16(sB + sw_off(r, kc), Bg + (size_t)r * KBY + kc * 16);
        }
    };

    load_stage(0); cp_commit();
    load_stage(1); cp_commit();
    load_stage(2); cp_commit();

    for (int kt = 0; kt < KT; kt++) {
        if (kt + 2 < KT) cp_wait<2>(); else cp_wait<0>();
        __syncthreads();
        int kn = kt + 3;
        if (kn < KT) load_stage(kn);
        cp_commit();

        uint32_t sA = smem + (kt & 3) * STAGE_BYTES;
        uint32_t sB = sA + ABYTES;
#pragma unroll
        for (int kk = 0; kk < 2; kk++) {   // two K=32 mma steps per 64B chunk
            uint32_t a[2][4];
#pragma unroll
            for (int mi = 0; mi < 2; mi++) {
                int r = wm * 32 + mi * 16 + (lane & 15);
                int kc = (kk << 1) | (lane >> 4);
                ldmx4(a[mi][0], a[mi][1], a[mi][2], a[mi][3], sA + sw_off(r, kc));
            }
            uint32_t bfr[8][2];
#pragma unroll
            for (int nj = 0; nj < 4; nj++) {
                int r = wn * 64 + nj * 16 + (lane & 7) + ((lane & 16) >> 1);
                int kc = (kk << 1) | ((lane >> 3) & 1);
                uint32_t t0, t1, t2, t3;
                ldmx4(t0, t1, t2, t3, sB + sw_off(r, kc));
                bfr[nj * 2][0] = t0; bfr[nj * 2][1] = t1;
                bfr[nj * 2 + 1][0] = t2; bfr[nj * 2 + 1][1] = t3;
            }
#pragma unroll
            for (int mi = 0; mi < 2; mi++)
#pragma unroll
                for (int ni = 0; ni < 8; ni++) mma16832(acc[mi][ni], a[mi], bfr[ni]);
        }
    }

    // epilogue: z = acc/64 + b1, h = gelu(z), store 4h as fp8
    const long crow = bm + wm * 32 + (lane >> 2);
#pragma unroll
    for (int mi = 0; mi < 2; mi++) {
#pragma unroll
        for (int ni = 0; ni < 8; ni++) {
            int col = wn * 64 + ni * 8 + ((lane & 3) << 1);
            float b0 = bias[col], b1 = bias[col + 1];
            float v0 = gelu_exact(acc[mi][ni][0] * INV_S1 + b0) * SH;
            float v1 = gelu_exact(acc[mi][ni][1] * INV_S1 + b1) * SH;
            float v2 = gelu_exact(acc[mi][ni][2] * INV_S1 + b0) * SH;
            float v3 = gelu_exact(acc[mi][ni][3] * INV_S1 + b1) * SH;
            long r0 = crow + mi * 16;
            *(uint16_t*)(g_Hf8 + r0 * HIDD + col) = pack2_e4m3(v0, v1);
            *(uint16_t*)(g_Hf8 + (r0 + 8) * HIDD + col) = pack2_e4m3(v2, v3);
        }
    }
}

// ---------------------------------------------------------------------------
// Kernel 3: GEMM2 (fp8)  Y = H @ W2^T + b2.  128x128 tiles, K-chunk 64 B,
// KT=4, 256 threads, 2 CTAs/SM, 4 stages (full K resident).
// ---------------------------------------------------------------------------
__global__ void __launch_bounds__(256, 2)
gemm2(const float* __restrict__ bias) {
    constexpr int ABYTES = 8192;    // 128 x 64 B
    constexpr int BBYTES = 8192;
    constexpr int STAGE_BYTES = ABYTES + BBYTES;  // 16 KB x 4 = 64 KB
    constexpr int KBY = 256, N = 4096, KT = 4;
    extern __shared__ __align__(128) uint8_t smem_raw[];
    const uint32_t smem = (uint32_t)__cvta_generic_to_shared(smem_raw);

    const int tid = threadIdx.x;
    const int lane = tid & 31, warp = tid >> 5;
    const int wm = warp >> 1, wn = warp & 1;
    const long bm = (long)blockIdx.y * 128;
    const long bn = (long)blockIdx.x * 128;

    float acc[2][8][4];
#pragma unroll
    for (int i = 0; i < 2; i++)
#pragma unroll
        for (int j = 0; j < 8; j++)
#pragma unroll
            for (int k = 0; k < 4; k++) acc[i][j][k] = 0.0f;

    auto load_stage = [&](int kt) {
        const uint8_t* Ag = g_Hf8 + bm * KBY + kt * 64;
        const uint8_t* Bg = g_W2f8 + bn * KBY + kt * 64;
        uint32_t sA = smem + (kt & 3) * STAGE_BYTES;
        uint32_t sB = sA + ABYTES;
#pragma unroll
        for (int i = 0; i < 2; i++) {
            int q = tid + (i << 8);
            int r = q >> 2, kc = q & 3;
            cp_async16(sA + sw_off(r, kc), Ag + (size_t)r * KBY + kc * 16);
        }
#pragma unroll
        for (int i = 0; i < 2; i++) {
            int q = tid + (i << 8);
            int r = q >> 2, kc = q & 3;
            cp_async16(sB + sw_off(r, kc), Bg + (size_t)r * KBY + kc * 16);
        }
    };

    load_stage(0); cp_commit();
    load_stage(1); cp_commit();
    load_stage(2); cp_commit();

    for (int kt = 0; kt < KT; kt++) {
        if (kt + 2 < KT) cp_wait<2>(); else cp_wait<0>();
        __syncthreads();
        int kn = kt + 3;
        if (kn < KT) load_stage(kn);
        cp_commit();

        uint32_t sA = smem + (kt & 3) * STAGE_BYTES;
        uint32_t sB = sA + ABYTES;
#pragma unroll
        for (int kk = 0; kk < 2; kk++) {
            uint32_t a[2][4];
#pragma unroll
            for (int mi = 0; mi < 2; mi++) {
                int r = wm * 32 + mi * 16 + (lane & 15);
                int kc = (kk << 1) | (lane >> 4);
                ldmx4(a[mi][0], a[mi][1], a[mi][2], a[mi][3], sA + sw_off(r, kc));
            }
            uint32_t bfr[8][2];
#pragma unroll
            for (int nj = 0; nj < 4; nj++) {
                int r = wn * 64 + nj * 16 + (lane & 7) + ((lane & 16) >> 1);
                int kc = (kk << 1) | ((lane >> 3) & 1);
                uint32_t t0, t1, t2, t3;
                ldmx4(t0, t1, t2, t3, sB + sw_off(r, kc));
                bfr[nj * 2][0] = t0; bfr[nj * 2][1] = t1;
                bfr[nj * 2 + 1][0] = t2; bfr[nj * 2 + 1][1] = t3;
            }
#pragma unroll
            for (int mi = 0; mi < 2; mi++)
#pragma unroll
                for (int ni = 0; ni < 8; ni++) mma16832(acc[mi][ni], a[mi], bfr[ni]);
        }
    }

    const long crow = bm + wm * 32 + (lane >> 2);
#pragma unroll
    for (int mi = 0; mi < 2; mi++) {
#pragma unroll
        for (int ni = 0; ni < 8; ni++) {
            long col = bn + wn * 64 + ni * 8 + ((lane & 3) << 1);
            float b0 = bias[col], b1 = bias[col + 1];
            float v0 = acc[mi][ni][0] * INV_S2 + b0;
            float v1 = acc[mi][ni][1] * INV_S2 + b1;
            float v2 = acc[mi][ni][2] * INV_S2 + b0;
            float v3 = acc[mi][ni][3] * INV_S2 + b1;
            long r0 = crow + mi * 16;
            *(__nv_bfloat162*)(g_Y + r0 * N + col) = __floats2bfloat162_rn(v0, v1);
            *(__nv_bfloat162*)(g_Y + (r0 + 8) * N + col) =
                __floats2bfloat162_rn(v2, v3);
        }
    }
}

// ---------------------------------------------------------------------------
// Kernel 4: gather-fold + residual
// out = x + softplus(alpha_raw) * fold(Y)/norm
// ---------------------------------------------------------------------------
__global__ void fold_kernel(const float* __restrict__ x,
                            const float* __restrict__ alpha_raw,
                            float* __restrict__ out) {
    int t = blockIdx.x * 256 + threadIdx.x;  // 4,194,304 threads
    int w0 = (t & 63) << 2;
    int h = (t >> 6) & 255;
    int c = (t >> 14) & 63;
    int b = t >> 20;

    float alpha = log1pf(__expf(alpha_raw[0]));

    int ih_lo = max(0, (h - 4) >> 2);
    int ih_hi = min(62, h >> 2);
    int iw_lo = max(0, (w0 - 4) >> 2);
    int iw_hi = min(62, w0 >> 2);
    int cnt = (ih_hi - ih_lo + 1) * (iw_hi - iw_lo + 1);

    float s0 = 0.f, s1 = 0.f, s2 = 0.f, s3 = 0.f;
    for (int ih = ih_lo; ih <= ih_hi; ih++) {
        int kh = h - 4 * ih;
        for (int iw = iw_lo; iw <= iw_hi; iw++) {
            int kw0 = w0 - 4 * iw;
            size_t m = (size_t)b * NPATCH + ih * NP + iw;
            const __nv_bfloat162* p =
                (const __nv_bfloat162*)(g_Y + m * IND + c * 64 + kh * 8 + kw0);
            __nv_bfloat162 v01 = p[0];
            __nv_bfloat162 v23 = p[1];
            s0 += __low2float(v01); s1 += __high2float(v01);
            s2 += __low2float(v23); s3 += __high2float(v23);
        }
    }
    float sc = alpha / (float)cnt;
    size_t xi = (size_t)t * 4;
    float4 xv = *(const float4*)(x + xi);
    float4 o;
    o.x = fmaf(s0, sc, xv.x);
    o.y = fmaf(s1, sc, xv.y);
    o.z = fmaf(s2, sc, xv.z);
    o.w = fmaf(s3, sc, xv.w);
    *(float4*)(out + xi) = o;
}

// ---------------------------------------------------------------------------
// Launch
// ---------------------------------------------------------------------------
extern "C" void kernel_launch(void* const* d_in, const int* in_sizes, int n_in,
                              void* d_out, int out_size) {
    const float* x         = (const float*)d_in[0];
    const float* W1        = (const float*)d_in[1];
    const float* b1        = (const float*)d_in[2];
    const float* W2        = (const float*)d_in[3];
    const float* b2        = (const float*)d_in[4];
    const float* alpha_raw = (const float*)d_in[5];
    float* out             = (float*)d_out;

    const int SM1 = 4 * 24576;  // 96 KB
    const int SM2 = 4 * 16384;  // 64 KB
    cudaFuncSetAttribute(gemm1_fused,
                         cudaFuncAttributeMaxDynamicSharedMemorySize, SM1);
    cudaFuncSetAttribute(gemm2,
                         cudaFuncAttributeMaxDynamicSharedMemorySize, SM2);

    convert_weights<<<1024, 256>>>(W1, W2);
    convert_x<<<16384, 256>>>(x);
    // GEMM1 (+patchify): H = GELU(P @ W1^T + b1)  M=16000, N=256, K=4096
    gemm1_fused<<<125, 512, SM1>>>(b1);
    // GEMM2: Y = H @ W2^T + b2                    M=16000, N=4096, K=256
    gemm2<<<dim3(32, 125), 256, SM2>>>(b2);
    fold_kernel<<<16384, 256>>>(x, alpha_raw, out);
}